// round 13
// baseline (speedup 1.0000x reference)
#include <cuda_runtime.h>
#include <cuda_bf16.h>
#include <math.h>
#include <stdint.h>

#define HEADS 8
#define BATCH 4
#define CH    512
#define NTOK  2304          // 48*48
#define DQ    64
#define LOG2E 1.4426950408889634f
#define MAXC  60.0f         // fixed softmax offset (log2 domain)

// Scratch (allocation-free rule: __device__ globals)
__device__ float g_SC[BATCH * CH * NTOK];
__device__ __nv_bfloat16 g_Wh [4 * CH * CH];
__device__ __nv_bfloat16 g_Wl [4 * CH * CH];
__device__ __nv_bfloat16 g_xth[BATCH * NTOK * CH];
__device__ __nv_bfloat16 g_xtl[BATCH * NTOK * CH];
// token-major bf16 hi/lo Q,K: [b][h][n][64]   (Q pre-scaled by log2(e))
__device__ __nv_bfloat16 g_Qth[BATCH * HEADS * NTOK * DQ];
__device__ __nv_bfloat16 g_Qtl[BATCH * HEADS * NTOK * DQ];
__device__ __nv_bfloat16 g_Kth[BATCH * HEADS * NTOK * DQ];
__device__ __nv_bfloat16 g_Ktl[BATCH * HEADS * NTOK * DQ];
// V split: [b][ch][n]
__device__ __nv_bfloat16 g_Vh[BATCH * CH * NTOK];
__device__ __nv_bfloat16 g_Vl[BATCH * CH * NTOK];

// ---------------------------------------------------------------------------
// PTX helpers (compute_100-safe: cp.async, ldmatrix, mma.sync)
// ---------------------------------------------------------------------------
__device__ __forceinline__ void cp_async16(uint32_t dst, const void* src) {
    asm volatile("cp.async.cg.shared.global [%0], [%1], 16;\n" :: "r"(dst), "l"(src));
}
__device__ __forceinline__ void cp_commit() {
    asm volatile("cp.async.commit_group;\n" ::);
}
template<int N> __device__ __forceinline__ void cp_wait() {
    asm volatile("cp.async.wait_group %0;\n" :: "n"(N));
}
__device__ __forceinline__ uint32_t smem_u32(const void* p) {
    return (uint32_t)__cvta_generic_to_shared(p);
}
__device__ __forceinline__ void ldsm4(uint32_t& r0, uint32_t& r1, uint32_t& r2,
                                      uint32_t& r3, uint32_t a) {
    asm volatile("ldmatrix.sync.aligned.m8n8.x4.shared.b16 {%0,%1,%2,%3}, [%4];"
                 : "=r"(r0), "=r"(r1), "=r"(r2), "=r"(r3) : "r"(a));
}
__device__ __forceinline__ void ldsm2(uint32_t& r0, uint32_t& r1, uint32_t a) {
    asm volatile("ldmatrix.sync.aligned.m8n8.x2.shared.b16 {%0,%1}, [%2];"
                 : "=r"(r0), "=r"(r1) : "r"(a));
}
__device__ __forceinline__ void mma_bf16(float& c0, float& c1, float& c2, float& c3,
                                         uint32_t a0, uint32_t a1, uint32_t a2, uint32_t a3,
                                         uint32_t b0, uint32_t b1) {
    asm volatile("mma.sync.aligned.m16n8k16.row.col.f32.bf16.bf16.f32 "
                 "{%0,%1,%2,%3}, {%4,%5,%6,%7}, {%8,%9}, {%0,%1,%2,%3};"
                 : "+f"(c0), "+f"(c1), "+f"(c2), "+f"(c3)
                 : "r"(a0), "r"(a1), "r"(a2), "r"(a3), "r"(b0), "r"(b1));
}
__device__ __forceinline__ uint32_t pack_bf16x2(float lo, float hi) {
    uint32_t r;
    asm("cvt.rn.bf16x2.f32 %0, %1, %2;" : "=r"(r) : "f"(hi), "f"(lo));
    return r;
}
__device__ __forceinline__ float ex2f(float x) {
    float r;
    asm("ex2.approx.f32 %0, %1;" : "=f"(r) : "f"(x));
    return r;
}

// ---------------------------------------------------------------------------
// prep kernels
// ---------------------------------------------------------------------------
__global__ void prep_w_kernel(const float* __restrict__ Wq, const float* __restrict__ Wk,
                              const float* __restrict__ Wv, const float* __restrict__ Wsc)
{
    const float* W = (blockIdx.y == 0) ? Wq : (blockIdx.y == 1) ? Wk
                   : (blockIdx.y == 2) ? Wv : Wsc;
    const int idx = blockIdx.x * 256 + threadIdx.x;
    const float a = W[idx];
    const __nv_bfloat16 h = __float2bfloat16(a);
    const size_t o = (size_t)blockIdx.y * CH * CH + idx;
    g_Wh[o] = h;
    g_Wl[o] = __float2bfloat16(a - __bfloat162float(h));
}

__global__ void prep_x_kernel(const float* __restrict__ x)
{
    __shared__ float t[32][33];
    const int b  = blockIdx.z;
    const int n0 = blockIdx.x * 32;
    const int c0 = blockIdx.y * 32;
    const int tx = threadIdx.x, ty = threadIdx.y;
    const float* src = x + ((size_t)b * CH + c0) * NTOK + n0;
#pragma unroll
    for (int i = 0; i < 32; i += 8)
        t[ty + i][tx] = src[(size_t)(ty + i) * NTOK + tx];
    __syncthreads();
    __nv_bfloat16* dh = g_xth + ((size_t)b * NTOK + n0) * CH + c0;
    __nv_bfloat16* dl = g_xtl + ((size_t)b * NTOK + n0) * CH + c0;
#pragma unroll
    for (int i = 0; i < 32; i += 8) {
        const float v = t[tx][ty + i];
        const __nv_bfloat16 h = __float2bfloat16(v);
        dh[(size_t)(ty + i) * CH + tx] = h;
        dl[(size_t)(ty + i) * CH + tx] = __float2bfloat16(v - __bfloat162float(h));
    }
}

// ---------------------------------------------------------------------------
// Projection GEMM via mma.sync bf16 3-term split + fused output formatting.
// 2 CTAs/SM: smem 80KB x2 = 160KB, regs capped at 128.
// ---------------------------------------------------------------------------
#define PJ_ARR_BYTES   10240
#define PJ_STAGE_BYTES (4 * PJ_ARR_BYTES)
#define PJ_SMEM_BYTES  (2 * PJ_STAGE_BYTES)

__global__ __launch_bounds__(256, 2) void proj_mma_kernel(void)
{
    extern __shared__ char smem[];
    const uint32_t sbase = smem_u32(smem);
    const int tid = threadIdx.x;
    const int wid = tid >> 5;
    const int lid = tid & 31;

    const int which = blockIdx.z & 3;
    const int b     = blockIdx.z >> 2;
    const int n0    = blockIdx.x * 128;
    const int o0    = blockIdx.y * 128;

    const __nv_bfloat16* Ah_g = g_Wh + (size_t)which * CH * CH + (size_t)o0 * CH;
    const __nv_bfloat16* Al_g = g_Wl + (size_t)which * CH * CH + (size_t)o0 * CH;
    const __nv_bfloat16* Bh_g = g_xth + ((size_t)b * NTOK + n0) * CH;
    const __nv_bfloat16* Bl_g = g_xtl + ((size_t)b * NTOK + n0) * CH;

    const int warp_m = wid >> 2;
    const int warp_n = wid & 3;
    const int mbase = warp_m * 64;
    const int nbase = warp_n * 32;

    auto load_chunk = [&](int buf, int chunk) {
        const int c0 = chunk * 32;
        const uint32_t sb = sbase + buf * PJ_STAGE_BYTES;
#pragma unroll
        for (int t = 0; t < 8; t++) {
            const int idx = tid + t * 256;
            const int arr = idx >> 9;
            const int i   = idx & 511;
            const int row = i >> 2;
            const int q16 = (i & 3) * 16;
            const uint32_t dst = sb + arr * PJ_ARR_BYTES + row * 80 + q16;
            const __nv_bfloat16* base = (arr == 0) ? Ah_g : (arr == 1) ? Al_g
                                      : (arr == 2) ? Bh_g : Bl_g;
            cp_async16(dst, (const char*)(base + (size_t)row * CH + c0) + q16);
        }
        cp_commit();
    };

    float c[4][4][4];
#pragma unroll
    for (int mt = 0; mt < 4; mt++)
#pragma unroll
        for (int nt = 0; nt < 4; nt++)
#pragma unroll
            for (int k = 0; k < 4; k++) c[mt][nt][k] = 0.f;

    load_chunk(0, 0);

    for (int chunk = 0; chunk < 16; chunk++) {
        const int buf = chunk & 1;
        if (chunk + 1 < 16) {
            load_chunk(buf ^ 1, chunk + 1);
            cp_wait<1>();
        } else {
            cp_wait<0>();
        }
        __syncthreads();

        const uint32_t sb = sbase + buf * PJ_STAGE_BYTES;
        const int arow = (lid & 7) + ((lid & 8) ? 8 : 0);
        const int akob = (lid & 16) ? 16 : 0;
        const int brow = lid & 7;
        const int bkob = (lid & 8) ? 16 : 0;

#pragma unroll
        for (int kstep = 0; kstep < 2; kstep++) {
            const int kb = kstep * 32;

            uint32_t bh[4][2], bl[4][2];
#pragma unroll
            for (int nt = 0; nt < 4; nt++) {
                const uint32_t ba = sb + 2 * PJ_ARR_BYTES +
                                    (nbase + nt * 8 + brow) * 80 + bkob + kb;
                ldsm2(bh[nt][0], bh[nt][1], ba);
                ldsm2(bl[nt][0], bl[nt][1], ba + PJ_ARR_BYTES);
            }

#pragma unroll
            for (int mt = 0; mt < 4; mt++) {
                const uint32_t aa = sb + (mbase + mt * 16 + arow) * 80 + akob + kb;
                uint32_t ah[4], al[4];
                ldsm4(ah[0], ah[1], ah[2], ah[3], aa);
                ldsm4(al[0], al[1], al[2], al[3], aa + PJ_ARR_BYTES);
#pragma unroll
                for (int nt = 0; nt < 4; nt++) {
                    mma_bf16(c[mt][nt][0], c[mt][nt][1], c[mt][nt][2], c[mt][nt][3],
                             ah[0], ah[1], ah[2], ah[3], bh[nt][0], bh[nt][1]);
                    mma_bf16(c[mt][nt][0], c[mt][nt][1], c[mt][nt][2], c[mt][nt][3],
                             ah[0], ah[1], ah[2], ah[3], bl[nt][0], bl[nt][1]);
                    mma_bf16(c[mt][nt][0], c[mt][nt][1], c[mt][nt][2], c[mt][nt][3],
                             al[0], al[1], al[2], al[3], bh[nt][0], bh[nt][1]);
                }
            }
        }
        __syncthreads();
    }

    // ---- fused epilogue: stage fp32 tile in smem [128 m][132], then format
    float* epi = (float*)smem;
#pragma unroll
    for (int mt = 0; mt < 4; mt++) {
#pragma unroll
        for (int nt = 0; nt < 4; nt++) {
            const int m = mbase + mt * 16 + (lid >> 2);
            const int nn = nbase + nt * 8 + 2 * (lid & 3);
            epi[m * 132 + nn]           = c[mt][nt][0];
            epi[m * 132 + nn + 1]       = c[mt][nt][1];
            epi[(m + 8) * 132 + nn]     = c[mt][nt][2];
            epi[(m + 8) * 132 + nn + 1] = c[mt][nt][3];
        }
    }
    __syncthreads();

    if (which == 3) {
        float* outb = g_SC + ((size_t)b * CH + o0) * NTOK + n0;
#pragma unroll
        for (int j = 0; j < 16; j++) {
            const int idx = tid + j * 256;
            const int m  = idx >> 5;
            const int n4 = (idx & 31) * 4;
            float4 v = make_float4(epi[m * 132 + n4],     epi[m * 132 + n4 + 1],
                                   epi[m * 132 + n4 + 2], epi[m * 132 + n4 + 3]);
            *(float4*)&outb[(size_t)m * NTOK + n4] = v;
        }
    } else if (which == 2) {
        __nv_bfloat16* vh = g_Vh + ((size_t)b * CH + o0) * NTOK + n0;
        __nv_bfloat16* vl = g_Vl + ((size_t)b * CH + o0) * NTOK + n0;
#pragma unroll
        for (int j = 0; j < 16; j++) {
            const int idx = tid + j * 256;
            const int m  = idx >> 5;
            const int n4 = (idx & 31) * 4;
            const float v0 = epi[m * 132 + n4],     v1 = epi[m * 132 + n4 + 1];
            const float v2 = epi[m * 132 + n4 + 2], v3 = epi[m * 132 + n4 + 3];
            const uint32_t h01 = pack_bf16x2(v0, v1);
            const uint32_t h23 = pack_bf16x2(v2, v3);
            const uint32_t l01 = pack_bf16x2(v0 - __uint_as_float(h01 << 16),
                                             v1 - __uint_as_float(h01 & 0xffff0000u));
            const uint32_t l23 = pack_bf16x2(v2 - __uint_as_float(h23 << 16),
                                             v3 - __uint_as_float(h23 & 0xffff0000u));
            *(uint2*)(vh + (size_t)m * NTOK + n4) = make_uint2(h01, h23);
            *(uint2*)(vl + (size_t)m * NTOK + n4) = make_uint2(l01, l23);
        }
    } else {
        const float qscale = (which == 0) ? LOG2E : 1.0f;
        const int tok = tid >> 1;
        const int hp  = tid & 1;
        const int head = (o0 >> 6) + hp;
        __nv_bfloat16* qh = ((which == 0) ? g_Qth : g_Kth) +
            ((size_t)(b * HEADS + head) * NTOK + n0 + tok) * DQ;
        __nv_bfloat16* ql = ((which == 0) ? g_Qtl : g_Ktl) +
            ((size_t)(b * HEADS + head) * NTOK + n0 + tok) * DQ;
#pragma unroll
        for (int g8 = 0; g8 < 8; g8++) {
            uint32_t hw[4], lw[4];
#pragma unroll
            for (int p = 0; p < 4; p++) {
                const int d = g8 * 8 + p * 2;
                const float v0 = epi[(hp * 64 + d) * 132 + tok] * qscale;
                const float v1 = epi[(hp * 64 + d + 1) * 132 + tok] * qscale;
                const uint32_t hh = pack_bf16x2(v0, v1);
                hw[p] = hh;
                lw[p] = pack_bf16x2(v0 - __uint_as_float(hh << 16),
                                    v1 - __uint_as_float(hh & 0xffff0000u));
            }
            ((uint4*)qh)[g8] = make_uint4(hw[0], hw[1], hw[2], hw[3]);
            ((uint4*)ql)[g8] = make_uint4(lw[0], lw[1], lw[2], lw[3]);
        }
    }
}

// ---------------------------------------------------------------------------
// Flash attention: 128-thr CTAs, q-tile 64, K/V tile 64, dbl-buffered.
// ONE __syncthreads per tile (load issued after the sync); K and V in
// SEPARATE commit groups so GEMM1 never waits on V bytes.
// ---------------------------------------------------------------------------
#define AT_VOFF  36864              // K stages [0, 36864), V stages [36864, 73728)
#define AT_SMEM  73728
#define NKT      (NTOK / 64)        // 36

__global__ __launch_bounds__(128, 3) void attn_mma_kernel(
    const float* __restrict__ gamma, float* __restrict__ outp)
{
    extern __shared__ char sm[];
    const uint32_t sb = smem_u32(sm);
    const int tid = threadIdx.x, wid = tid >> 5, lid = tid & 31;
    const int q0 = blockIdx.x * 64, h = blockIdx.y, b = blockIdx.z;
    const int bh = b * HEADS + h;

    const __nv_bfloat16* Qh = g_Qth + (size_t)bh * NTOK * DQ;
    const __nv_bfloat16* Ql = g_Qtl + (size_t)bh * NTOK * DQ;
    const __nv_bfloat16* Kh = g_Kth + (size_t)bh * NTOK * DQ;
    const __nv_bfloat16* Kl = g_Ktl + (size_t)bh * NTOK * DQ;
    const __nv_bfloat16* Vh = g_Vh + (size_t)(b * CH + h * DQ) * NTOK;
    const __nv_bfloat16* Vl = g_Vl + (size_t)(b * CH + h * DQ) * NTOK;
    const float* SC = g_SC + (size_t)(b * CH + h * DQ) * NTOK;

    auto load_k = [&](int st, int kt) {
        const int m0 = kt * 64;
        const uint32_t kst = sb + st * 18432;
#pragma unroll
        for (int j = 0; j < 8; j++) {
            const int idx = tid + j * 128;              // 0..1023
            const int hl = idx >> 9;
            const int i  = idx & 511;
            const int r  = i >> 3, cc = i & 7;
            const __nv_bfloat16* s = (hl ? Kl : Kh) + (size_t)(m0 + r) * DQ + cc * 8;
            cp_async16(kst + hl * 9216 + r * 144 + cc * 16, s);
        }
        cp_commit();
    };
    auto load_v = [&](int st, int kt) {
        const int m0 = kt * 64;
        const uint32_t vst = sb + AT_VOFF + st * 18432;
#pragma unroll
        for (int j = 0; j < 8; j++) {
            const int idx = tid + j * 128;              // 0..1023
            const int hl = idx >> 9;
            const int i  = idx & 511;
            const int r  = i >> 3, cc = i & 7;
            const __nv_bfloat16* s = (hl ? Vl : Vh) + (size_t)r * NTOK + m0 + cc * 8;
            cp_async16(vst + hl * 9216 + r * 144 + cc * 16, s);
        }
        cp_commit();
    };

    load_k(0, 0);
    load_v(0, 0);

    const int qw = wid * 16;
    const int brow = (lid & 7) + ((lid & 16) ? 8 : 0);
    const int bkob = (lid & 8) ? 16 : 0;

    // ---- Q fragments direct from gmem (m16n8k16 A layout)
    uint32_t qa_h[4][4], qa_l[4][4];
    {
        const int r0 = q0 + qw + (lid >> 2);
        const int cb = (lid & 3) * 2;
#pragma unroll
        for (int g = 0; g < 4; g++) {
            const size_t o0v = (size_t)r0 * DQ + g * 16 + cb;
            const size_t o1v = (size_t)(r0 + 8) * DQ + g * 16 + cb;
            qa_h[g][0] = *(const uint32_t*)(Qh + o0v);
            qa_h[g][1] = *(const uint32_t*)(Qh + o1v);
            qa_h[g][2] = *(const uint32_t*)(Qh + o0v + 8);
            qa_h[g][3] = *(const uint32_t*)(Qh + o1v + 8);
            qa_l[g][0] = *(const uint32_t*)(Ql + o0v);
            qa_l[g][1] = *(const uint32_t*)(Ql + o1v);
            qa_l[g][2] = *(const uint32_t*)(Ql + o0v + 8);
            qa_l[g][3] = *(const uint32_t*)(Ql + o1v + 8);
        }
    }

    float acc[8][4];
#pragma unroll
    for (int t = 0; t < 8; t++)
#pragma unroll
        for (int k = 0; k < 4; k++) acc[t][k] = 0.f;
    float sum0 = 0.f, sum1 = 0.f;

    for (int kt = 0; kt < NKT; kt++) {
        const int st = kt & 1;
        // K(kt) ready (V(kt) may still be in flight)
        cp_wait<1>();
        __syncthreads();   // also guarantees all warps done reading buffers of kt-1

        if (kt + 1 < NKT) {
            load_k(st ^ 1, kt + 1);
            load_v(st ^ 1, kt + 1);
        }

        // ---- GEMM1: S = Q K^T (3-term), tile 64x64
        float s[8][4];
#pragma unroll
        for (int t = 0; t < 8; t++)
#pragma unroll
            for (int k = 0; k < 4; k++) s[t][k] = 0.f;

        const uint32_t kb = sb + st * 18432;
#pragma unroll
        for (int g = 0; g < 4; g++) {
#pragma unroll
            for (int tp = 0; tp < 4; tp++) {
                const uint32_t a = kb + (tp * 16 + brow) * 144 + bkob + g * 32;
                uint32_t kh0, kh1, kh2, kh3, kl0, kl1, kl2, kl3;
                ldsm4(kh0, kh1, kh2, kh3, a);
                ldsm4(kl0, kl1, kl2, kl3, a + 9216);
                mma_bf16(s[2*tp][0], s[2*tp][1], s[2*tp][2], s[2*tp][3],
                         qa_h[g][0], qa_h[g][1], qa_h[g][2], qa_h[g][3], kh0, kh1);
                mma_bf16(s[2*tp][0], s[2*tp][1], s[2*tp][2], s[2*tp][3],
                         qa_h[g][0], qa_h[g][1], qa_h[g][2], qa_h[g][3], kl0, kl1);
                mma_bf16(s[2*tp][0], s[2*tp][1], s[2*tp][2], s[2*tp][3],
                         qa_l[g][0], qa_l[g][1], qa_l[g][2], qa_l[g][3], kh0, kh1);
                mma_bf16(s[2*tp+1][0], s[2*tp+1][1], s[2*tp+1][2], s[2*tp+1][3],
                         qa_h[g][0], qa_h[g][1], qa_h[g][2], qa_h[g][3], kh2, kh3);
                mma_bf16(s[2*tp+1][0], s[2*tp+1][1], s[2*tp+1][2], s[2*tp+1][3],
                         qa_h[g][0], qa_h[g][1], qa_h[g][2], qa_h[g][3], kl2, kl3);
                mma_bf16(s[2*tp+1][0], s[2*tp+1][1], s[2*tp+1][2], s[2*tp+1][3],
                         qa_l[g][0], qa_l[g][1], qa_l[g][2], qa_l[g][3], kh2, kh3);
            }
        }

        // V(kt) ready (leaves K(kt+1), V(kt+1) in flight)
        if (kt + 1 < NKT) cp_wait<2>(); else cp_wait<0>();

        // ---- fixed-offset softmax: p = 2^(s - MAXC); accumulate partials
#pragma unroll
        for (int t = 0; t < 8; t++) {
            s[t][0] = ex2f(s[t][0] - MAXC); sum0 += s[t][0];
            s[t][1] = ex2f(s[t][1] - MAXC); sum0 += s[t][1];
            s[t][2] = ex2f(s[t][2] - MAXC); sum1 += s[t][2];
            s[t][3] = ex2f(s[t][3] - MAXC); sum1 += s[t][3];
        }

        // ---- GEMM2: acc += P V (3-term)
        const uint32_t vb = sb + AT_VOFF + st * 18432;
#pragma unroll
        for (int g = 0; g < 4; g++) {
            uint32_t ph[4], pl[4];
#pragma unroll
            for (int half = 0; half < 2; half++) {
                const float p0 = s[2*g + half][0], p1 = s[2*g + half][1];
                const float p2 = s[2*g + half][2], p3 = s[2*g + half][3];
                const uint32_t h01 = pack_bf16x2(p0, p1);
                const uint32_t h23 = pack_bf16x2(p2, p3);
                ph[half ? 2 : 0] = h01;
                ph[half ? 3 : 1] = h23;
                pl[half ? 2 : 0] = pack_bf16x2(
                    p0 - __uint_as_float(h01 << 16),
                    p1 - __uint_as_float(h01 & 0xffff0000u));
                pl[half ? 3 : 1] = pack_bf16x2(
                    p2 - __uint_as_float(h23 << 16),
                    p3 - __uint_as_float(h23 & 0xffff0000u));
            }
#pragma unroll
            for (int dvp = 0; dvp < 4; dvp++) {
                const uint32_t a = vb + (dvp * 16 + brow) * 144 + bkob + g * 32;
                uint32_t vh0, vh1, vh2, vh3, vl0, vl1, vl2, vl3;
                ldsm4(vh0, vh1, vh2, vh3, a);
                ldsm4(vl0, vl1, vl2, vl3, a + 9216);
                mma_bf16(acc[2*dvp][0], acc[2*dvp][1], acc[2*dvp][2], acc[2*dvp][3],
                         ph[0], ph[1], ph[2], ph[3], vh0, vh1);
                mma_bf16(acc[2*dvp][0], acc[2*dvp][1], acc[2*dvp][2], acc[2*dvp][3],
                         ph[0], ph[1], ph[2], ph[3], vl0, vl1);
                mma_bf16(acc[2*dvp][0], acc[2*dvp][1], acc[2*dvp][2], acc[2*dvp][3],
                         pl[0], pl[1], pl[2], pl[3], vh0, vh1);
                mma_bf16(acc[2*dvp+1][0], acc[2*dvp+1][1], acc[2*dvp+1][2], acc[2*dvp+1][3],
                         ph[0], ph[1], ph[2], ph[3], vh2, vh3);
                mma_bf16(acc[2*dvp+1][0], acc[2*dvp+1][1], acc[2*dvp+1][2], acc[2*dvp+1][3],
                         ph[0], ph[1], ph[2], ph[3], vl2, vl3);
                mma_bf16(acc[2*dvp+1][0], acc[2*dvp+1][1], acc[2*dvp+1][2], acc[2*dvp+1][3],
                         pl[0], pl[1], pl[2], pl[3], vh2, vh3);
            }
        }
        // no end-of-iteration sync: next iteration's top sync provides the
        // read-protection before any buffer is overwritten.
    }

    // ---- row-sum reduction across the quad
    sum0 += __shfl_xor_sync(0xffffffffu, sum0, 1);
    sum0 += __shfl_xor_sync(0xffffffffu, sum0, 2);
    sum1 += __shfl_xor_sync(0xffffffffu, sum1, 1);
    sum1 += __shfl_xor_sync(0xffffffffu, sum1, 2);
    const float inv0 = 1.f / sum0, inv1 = 1.f / sum1;

    // ---- epilogue: acc/l -> smem [64 dv][68 q] (K buffer 0 region; last read
    // of that buffer was iter NKT-2, and every warp here passed iter NKT-1's
    // top sync) -> fused gamma*out + sc
    float* epi = (float*)sm;
    const int qr = qw + (lid >> 2);
#pragma unroll
    for (int t = 0; t < 8; t++) {
        const int dv = t * 8 + 2 * (lid & 3);
        epi[dv * 68 + qr]           = acc[t][0] * inv0;
        epi[(dv + 1) * 68 + qr]     = acc[t][1] * inv0;
        epi[dv * 68 + qr + 8]       = acc[t][2] * inv1;
        epi[(dv + 1) * 68 + qr + 8] = acc[t][3] * inv1;
    }
    __syncthreads();

#pragma unroll
    for (int j = 0; j < 8; j++) {
        const int idx = tid + j * 128;          // 0..1023 float4s (64 dv x 16 q4)
        const int r = idx >> 4;
        const int c4 = (idx & 15) * 4;
        const int ch = h * DQ + r;
        const float g = gamma[ch];
        float4 v = make_float4(epi[r * 68 + c4],     epi[r * 68 + c4 + 1],
                               epi[r * 68 + c4 + 2], epi[r * 68 + c4 + 3]);
        float4 scv = *(const float4*)&SC[(size_t)r * NTOK + q0 + c4];
        float4 o = make_float4(g * v.x + scv.x, g * v.y + scv.y,
                               g * v.z + scv.z, g * v.w + scv.w);
        *(float4*)&outp[((size_t)b * CH + ch) * NTOK + q0 + c4] = o;
    }
}

// ---------------------------------------------------------------------------
extern "C" void kernel_launch(void* const* d_in, const int* in_sizes, int n_in,
                              void* d_out, int out_size)
{
    const float* x     = (const float*)d_in[0];
    const float* Wq    = (const float*)d_in[1];
    const float* Wk    = (const float*)d_in[2];
    const float* Wv    = (const float*)d_in[3];
    const float* Wsc   = (const float*)d_in[4];
    const float* gamma = (const float*)d_in[5];
    float* out = (float*)d_out;

    prep_w_kernel<<<dim3(CH * CH / 256, 4), 256>>>(Wq, Wk, Wv, Wsc);
    prep_x_kernel<<<dim3(NTOK / 32, CH / 32, BATCH), dim3(32, 8)>>>(x);

    cudaFuncSetAttribute(proj_mma_kernel, cudaFuncAttributeMaxDynamicSharedMemorySize,
                         PJ_SMEM_BYTES);
    proj_mma_kernel<<<dim3(NTOK / 128, CH / 128, 16), 256, PJ_SMEM_BYTES>>>();

    cudaFuncSetAttribute(attn_mma_kernel, cudaFuncAttributeMaxDynamicSharedMemorySize,
                         AT_SMEM);
    attn_mma_kernel<<<dim3(NTOK / 64, HEADS, BATCH), 128, AT_SMEM>>>(gamma, out);
}

// round 15
// speedup vs baseline: 1.0206x; 1.0206x over previous
#include <cuda_runtime.h>
#include <cuda_bf16.h>
#include <math.h>
#include <stdint.h>

#define HEADS 8
#define BATCH 4
#define CH    512
#define NTOK  2304          // 48*48
#define DQ    64
#define LOG2E 1.4426950408889634f
#define MAXC  60.0f         // fixed softmax offset (log2 domain)

// Scratch (allocation-free rule: __device__ globals)
__device__ float g_SC[BATCH * CH * NTOK];
__device__ __nv_bfloat16 g_Wh [4 * CH * CH];
__device__ __nv_bfloat16 g_Wl [4 * CH * CH];
__device__ __nv_bfloat16 g_xth[BATCH * NTOK * CH];
__device__ __nv_bfloat16 g_xtl[BATCH * NTOK * CH];
// token-major bf16 hi/lo Q,K: [b][h][n][64]   (Q pre-scaled by log2(e))
__device__ __nv_bfloat16 g_Qth[BATCH * HEADS * NTOK * DQ];
__device__ __nv_bfloat16 g_Qtl[BATCH * HEADS * NTOK * DQ];
__device__ __nv_bfloat16 g_Kth[BATCH * HEADS * NTOK * DQ];
__device__ __nv_bfloat16 g_Ktl[BATCH * HEADS * NTOK * DQ];
// V split: [b][ch][n]
__device__ __nv_bfloat16 g_Vh[BATCH * CH * NTOK];
__device__ __nv_bfloat16 g_Vl[BATCH * CH * NTOK];

// ---------------------------------------------------------------------------
// PTX helpers (compute_100-safe: cp.async, ldmatrix, mma.sync)
// ---------------------------------------------------------------------------
__device__ __forceinline__ void cp_async16(uint32_t dst, const void* src) {
    asm volatile("cp.async.cg.shared.global [%0], [%1], 16;\n" :: "r"(dst), "l"(src));
}
__device__ __forceinline__ void cp_commit() {
    asm volatile("cp.async.commit_group;\n" ::);
}
template<int N> __device__ __forceinline__ void cp_wait() {
    asm volatile("cp.async.wait_group %0;\n" :: "n"(N));
}
__device__ __forceinline__ uint32_t smem_u32(const void* p) {
    return (uint32_t)__cvta_generic_to_shared(p);
}
__device__ __forceinline__ void ldsm4(uint32_t& r0, uint32_t& r1, uint32_t& r2,
                                      uint32_t& r3, uint32_t a) {
    asm volatile("ldmatrix.sync.aligned.m8n8.x4.shared.b16 {%0,%1,%2,%3}, [%4];"
                 : "=r"(r0), "=r"(r1), "=r"(r2), "=r"(r3) : "r"(a));
}
__device__ __forceinline__ void ldsm2(uint32_t& r0, uint32_t& r1, uint32_t a) {
    asm volatile("ldmatrix.sync.aligned.m8n8.x2.shared.b16 {%0,%1}, [%2];"
                 : "=r"(r0), "=r"(r1) : "r"(a));
}
__device__ __forceinline__ void mma_bf16(float& c0, float& c1, float& c2, float& c3,
                                         uint32_t a0, uint32_t a1, uint32_t a2, uint32_t a3,
                                         uint32_t b0, uint32_t b1) {
    asm volatile("mma.sync.aligned.m16n8k16.row.col.f32.bf16.bf16.f32 "
                 "{%0,%1,%2,%3}, {%4,%5,%6,%7}, {%8,%9}, {%0,%1,%2,%3};"
                 : "+f"(c0), "+f"(c1), "+f"(c2), "+f"(c3)
                 : "r"(a0), "r"(a1), "r"(a2), "r"(a3), "r"(b0), "r"(b1));
}
__device__ __forceinline__ uint32_t pack_bf16x2(float lo, float hi) {
    uint32_t r;
    asm("cvt.rn.bf16x2.f32 %0, %1, %2;" : "=r"(r) : "f"(hi), "f"(lo));
    return r;
}
__device__ __forceinline__ float ex2f(float x) {
    float r;
    asm("ex2.approx.f32 %0, %1;" : "=f"(r) : "f"(x));
    return r;
}

// ---------------------------------------------------------------------------
// prep kernels
// ---------------------------------------------------------------------------
__global__ void prep_w_kernel(const float* __restrict__ Wq, const float* __restrict__ Wk,
                              const float* __restrict__ Wv, const float* __restrict__ Wsc)
{
    const float* W = (blockIdx.y == 0) ? Wq : (blockIdx.y == 1) ? Wk
                   : (blockIdx.y == 2) ? Wv : Wsc;
    const int idx = blockIdx.x * 256 + threadIdx.x;
    const float a = W[idx];
    const __nv_bfloat16 h = __float2bfloat16(a);
    const size_t o = (size_t)blockIdx.y * CH * CH + idx;
    g_Wh[o] = h;
    g_Wl[o] = __float2bfloat16(a - __bfloat162float(h));
}

__global__ void prep_x_kernel(const float* __restrict__ x)
{
    __shared__ float t[32][33];
    const int b  = blockIdx.z;
    const int n0 = blockIdx.x * 32;
    const int c0 = blockIdx.y * 32;
    const int tx = threadIdx.x, ty = threadIdx.y;
    const float* src = x + ((size_t)b * CH + c0) * NTOK + n0;
#pragma unroll
    for (int i = 0; i < 32; i += 8)
        t[ty + i][tx] = src[(size_t)(ty + i) * NTOK + tx];
    __syncthreads();
    __nv_bfloat16* dh = g_xth + ((size_t)b * NTOK + n0) * CH + c0;
    __nv_bfloat16* dl = g_xtl + ((size_t)b * NTOK + n0) * CH + c0;
#pragma unroll
    for (int i = 0; i < 32; i += 8) {
        const float v = t[tx][ty + i];
        const __nv_bfloat16 h = __float2bfloat16(v);
        dh[(size_t)(ty + i) * CH + tx] = h;
        dl[(size_t)(ty + i) * CH + tx] = __float2bfloat16(v - __bfloat162float(h));
    }
}

// ---------------------------------------------------------------------------
// Projection GEMM via mma.sync bf16 3-term split + fused output formatting.
// 2 CTAs/SM: smem 80KB x2 = 160KB, regs capped at 128.
// ---------------------------------------------------------------------------
#define PJ_ARR_BYTES   10240
#define PJ_STAGE_BYTES (4 * PJ_ARR_BYTES)
#define PJ_SMEM_BYTES  (2 * PJ_STAGE_BYTES)

__global__ __launch_bounds__(256, 2) void proj_mma_kernel(void)
{
    extern __shared__ char smem[];
    const uint32_t sbase = smem_u32(smem);
    const int tid = threadIdx.x;
    const int wid = tid >> 5;
    const int lid = tid & 31;

    const int which = blockIdx.z & 3;
    const int b     = blockIdx.z >> 2;
    const int n0    = blockIdx.x * 128;
    const int o0    = blockIdx.y * 128;

    const __nv_bfloat16* Ah_g = g_Wh + (size_t)which * CH * CH + (size_t)o0 * CH;
    const __nv_bfloat16* Al_g = g_Wl + (size_t)which * CH * CH + (size_t)o0 * CH;
    const __nv_bfloat16* Bh_g = g_xth + ((size_t)b * NTOK + n0) * CH;
    const __nv_bfloat16* Bl_g = g_xtl + ((size_t)b * NTOK + n0) * CH;

    const int warp_m = wid >> 2;
    const int warp_n = wid & 3;
    const int mbase = warp_m * 64;
    const int nbase = warp_n * 32;

    auto load_chunk = [&](int buf, int chunk) {
        const int c0 = chunk * 32;
        const uint32_t sb = sbase + buf * PJ_STAGE_BYTES;
#pragma unroll
        for (int t = 0; t < 8; t++) {
            const int idx = tid + t * 256;
            const int arr = idx >> 9;
            const int i   = idx & 511;
            const int row = i >> 2;
            const int q16 = (i & 3) * 16;
            const uint32_t dst = sb + arr * PJ_ARR_BYTES + row * 80 + q16;
            const __nv_bfloat16* base = (arr == 0) ? Ah_g : (arr == 1) ? Al_g
                                      : (arr == 2) ? Bh_g : Bl_g;
            cp_async16(dst, (const char*)(base + (size_t)row * CH + c0) + q16);
        }
        cp_commit();
    };

    float c[4][4][4];
#pragma unroll
    for (int mt = 0; mt < 4; mt++)
#pragma unroll
        for (int nt = 0; nt < 4; nt++)
#pragma unroll
            for (int k = 0; k < 4; k++) c[mt][nt][k] = 0.f;

    load_chunk(0, 0);

    for (int chunk = 0; chunk < 16; chunk++) {
        const int buf = chunk & 1;
        if (chunk + 1 < 16) {
            load_chunk(buf ^ 1, chunk + 1);
            cp_wait<1>();
        } else {
            cp_wait<0>();
        }
        __syncthreads();

        const uint32_t sb = sbase + buf * PJ_STAGE_BYTES;
        const int arow = (lid & 7) + ((lid & 8) ? 8 : 0);
        const int akob = (lid & 16) ? 16 : 0;
        const int brow = lid & 7;
        const int bkob = (lid & 8) ? 16 : 0;

#pragma unroll
        for (int kstep = 0; kstep < 2; kstep++) {
            const int kb = kstep * 32;

            uint32_t bh[4][2], bl[4][2];
#pragma unroll
            for (int nt = 0; nt < 4; nt++) {
                const uint32_t ba = sb + 2 * PJ_ARR_BYTES +
                                    (nbase + nt * 8 + brow) * 80 + bkob + kb;
                ldsm2(bh[nt][0], bh[nt][1], ba);
                ldsm2(bl[nt][0], bl[nt][1], ba + PJ_ARR_BYTES);
            }

#pragma unroll
            for (int mt = 0; mt < 4; mt++) {
                const uint32_t aa = sb + (mbase + mt * 16 + arow) * 80 + akob + kb;
                uint32_t ah[4], al[4];
                ldsm4(ah[0], ah[1], ah[2], ah[3], aa);
                ldsm4(al[0], al[1], al[2], al[3], aa + PJ_ARR_BYTES);
#pragma unroll
                for (int nt = 0; nt < 4; nt++) {
                    mma_bf16(c[mt][nt][0], c[mt][nt][1], c[mt][nt][2], c[mt][nt][3],
                             ah[0], ah[1], ah[2], ah[3], bh[nt][0], bh[nt][1]);
                    mma_bf16(c[mt][nt][0], c[mt][nt][1], c[mt][nt][2], c[mt][nt][3],
                             ah[0], ah[1], ah[2], ah[3], bl[nt][0], bl[nt][1]);
                    mma_bf16(c[mt][nt][0], c[mt][nt][1], c[mt][nt][2], c[mt][nt][3],
                             al[0], al[1], al[2], al[3], bh[nt][0], bh[nt][1]);
                }
            }
        }
        __syncthreads();
    }

    // ---- fused epilogue: stage fp32 tile in smem [128 m][132], then format
    float* epi = (float*)smem;
#pragma unroll
    for (int mt = 0; mt < 4; mt++) {
#pragma unroll
        for (int nt = 0; nt < 4; nt++) {
            const int m = mbase + mt * 16 + (lid >> 2);
            const int nn = nbase + nt * 8 + 2 * (lid & 3);
            epi[m * 132 + nn]           = c[mt][nt][0];
            epi[m * 132 + nn + 1]       = c[mt][nt][1];
            epi[(m + 8) * 132 + nn]     = c[mt][nt][2];
            epi[(m + 8) * 132 + nn + 1] = c[mt][nt][3];
        }
    }
    __syncthreads();

    if (which == 3) {
        float* outb = g_SC + ((size_t)b * CH + o0) * NTOK + n0;
#pragma unroll
        for (int j = 0; j < 16; j++) {
            const int idx = tid + j * 256;
            const int m  = idx >> 5;
            const int n4 = (idx & 31) * 4;
            float4 v = make_float4(epi[m * 132 + n4],     epi[m * 132 + n4 + 1],
                                   epi[m * 132 + n4 + 2], epi[m * 132 + n4 + 3]);
            *(float4*)&outb[(size_t)m * NTOK + n4] = v;
        }
    } else if (which == 2) {
        __nv_bfloat16* vh = g_Vh + ((size_t)b * CH + o0) * NTOK + n0;
        __nv_bfloat16* vl = g_Vl + ((size_t)b * CH + o0) * NTOK + n0;
#pragma unroll
        for (int j = 0; j < 16; j++) {
            const int idx = tid + j * 256;
            const int m  = idx >> 5;
            const int n4 = (idx & 31) * 4;
            const float v0 = epi[m * 132 + n4],     v1 = epi[m * 132 + n4 + 1];
            const float v2 = epi[m * 132 + n4 + 2], v3 = epi[m * 132 + n4 + 3];
            const uint32_t h01 = pack_bf16x2(v0, v1);
            const uint32_t h23 = pack_bf16x2(v2, v3);
            const uint32_t l01 = pack_bf16x2(v0 - __uint_as_float(h01 << 16),
                                             v1 - __uint_as_float(h01 & 0xffff0000u));
            const uint32_t l23 = pack_bf16x2(v2 - __uint_as_float(h23 << 16),
                                             v3 - __uint_as_float(h23 & 0xffff0000u));
            *(uint2*)(vh + (size_t)m * NTOK + n4) = make_uint2(h01, h23);
            *(uint2*)(vl + (size_t)m * NTOK + n4) = make_uint2(l01, l23);
        }
    } else {
        const float qscale = (which == 0) ? LOG2E : 1.0f;
        const int tok = tid >> 1;
        const int hp  = tid & 1;
        const int head = (o0 >> 6) + hp;
        __nv_bfloat16* qh = ((which == 0) ? g_Qth : g_Kth) +
            ((size_t)(b * HEADS + head) * NTOK + n0 + tok) * DQ;
        __nv_bfloat16* ql = ((which == 0) ? g_Qtl : g_Ktl) +
            ((size_t)(b * HEADS + head) * NTOK + n0 + tok) * DQ;
#pragma unroll
        for (int g8 = 0; g8 < 8; g8++) {
            uint32_t hw[4], lw[4];
#pragma unroll
            for (int p = 0; p < 4; p++) {
                const int d = g8 * 8 + p * 2;
                const float v0 = epi[(hp * 64 + d) * 132 + tok] * qscale;
                const float v1 = epi[(hp * 64 + d + 1) * 132 + tok] * qscale;
                const uint32_t hh = pack_bf16x2(v0, v1);
                hw[p] = hh;
                lw[p] = pack_bf16x2(v0 - __uint_as_float(hh << 16),
                                    v1 - __uint_as_float(hh & 0xffff0000u));
            }
            ((uint4*)qh)[g8] = make_uint4(hw[0], hw[1], hw[2], hw[3]);
            ((uint4*)ql)[g8] = make_uint4(lw[0], lw[1], lw[2], lw[3]);
        }
    }
}

// ---------------------------------------------------------------------------
// Flash attention: 128-thr CTAs, q-tile 64. K SINGLE-buffered, V DOUBLE-
// buffered; the ONLY consume-side wait is cp_wait<0> + __syncthreads at the
// top of each tile (race-free: all threads' K(kt)+V(kt) visible). load_v(kt+1)
// issued right after top sync (full-tile overlap); load_k(kt+1) issued after a
// mid-tile barrier that follows the last K read (overlapped by smax+GEMM2 h1).
// Half-tile score processing keeps live regs ~120.
// smem 55296/CTA -> 4 CTAs/SM, regs capped at 128.
// ---------------------------------------------------------------------------
#define AT_VOFF  18432              // K: [0,18432); V: 2 x 18432 at [18432,55296)
#define AT_SMEM  55296
#define NKT      (NTOK / 64)        // 36

__global__ __launch_bounds__(128, 4) void attn_mma_kernel(
    const float* __restrict__ gamma, float* __restrict__ outp)
{
    extern __shared__ char sm[];
    const uint32_t sb = smem_u32(sm);
    const int tid = threadIdx.x, wid = tid >> 5, lid = tid & 31;
    const int q0 = blockIdx.x * 64, h = blockIdx.y, b = blockIdx.z;
    const int bh = b * HEADS + h;

    const __nv_bfloat16* Qh = g_Qth + (size_t)bh * NTOK * DQ;
    const __nv_bfloat16* Ql = g_Qtl + (size_t)bh * NTOK * DQ;
    const __nv_bfloat16* Kh = g_Kth + (size_t)bh * NTOK * DQ;
    const __nv_bfloat16* Kl = g_Ktl + (size_t)bh * NTOK * DQ;
    const __nv_bfloat16* Vh = g_Vh + (size_t)(b * CH + h * DQ) * NTOK;
    const __nv_bfloat16* Vl = g_Vl + (size_t)(b * CH + h * DQ) * NTOK;
    const float* SC = g_SC + (size_t)(b * CH + h * DQ) * NTOK;

    auto load_k = [&](int kt) {                 // single K buffer at offset 0
        const int m0 = kt * 64;
#pragma unroll
        for (int j = 0; j < 8; j++) {
            const int idx = tid + j * 128;
            const int hl = idx >> 9;
            const int i  = idx & 511;
            const int r  = i >> 3, cc = i & 7;
            const __nv_bfloat16* s = (hl ? Kl : Kh) + (size_t)(m0 + r) * DQ + cc * 8;
            cp_async16(sb + hl * 9216 + r * 144 + cc * 16, s);
        }
        cp_commit();
    };
    auto load_v = [&](int kt, int buf) {        // double V buffers
        const int m0 = kt * 64;
        const uint32_t vst = sb + AT_VOFF + buf * 18432;
#pragma unroll
        for (int j = 0; j < 8; j++) {
            const int idx = tid + j * 128;
            const int hl = idx >> 9;
            const int i  = idx & 511;
            const int r  = i >> 3, cc = i & 7;
            const __nv_bfloat16* s = (hl ? Vl : Vh) + (size_t)r * NTOK + m0 + cc * 8;
            cp_async16(vst + hl * 9216 + r * 144 + cc * 16, s);
        }
        cp_commit();
    };

    load_k(0);
    load_v(0, 0);

    const int qw = wid * 16;
    const int brow = (lid & 7) + ((lid & 16) ? 8 : 0);
    const int bkob = (lid & 8) ? 16 : 0;

    // ---- Q fragments direct from gmem (m16n8k16 A layout)
    uint32_t qa_h[4][4], qa_l[4][4];
    {
        const int r0 = q0 + qw + (lid >> 2);
        const int cb = (lid & 3) * 2;
#pragma unroll
        for (int g = 0; g < 4; g++) {
            const size_t o0v = (size_t)r0 * DQ + g * 16 + cb;
            const size_t o1v = (size_t)(r0 + 8) * DQ + g * 16 + cb;
            qa_h[g][0] = *(const uint32_t*)(Qh + o0v);
            qa_h[g][1] = *(const uint32_t*)(Qh + o1v);
            qa_h[g][2] = *(const uint32_t*)(Qh + o0v + 8);
            qa_h[g][3] = *(const uint32_t*)(Qh + o1v + 8);
            qa_l[g][0] = *(const uint32_t*)(Ql + o0v);
            qa_l[g][1] = *(const uint32_t*)(Ql + o1v);
            qa_l[g][2] = *(const uint32_t*)(Ql + o0v + 8);
            qa_l[g][3] = *(const uint32_t*)(Ql + o1v + 8);
        }
    }

    float acc[8][4];
#pragma unroll
    for (int t = 0; t < 8; t++)
#pragma unroll
        for (int k = 0; k < 4; k++) acc[t][k] = 0.f;
    float sum0 = 0.f, sum1 = 0.f;

    // GEMM1 for k-token rows tp in {tp0, tp0+1} -> s[0..3]
    auto gemm1_half = [&](float (*s)[4], int tp0) {
#pragma unroll
        for (int t = 0; t < 4; t++)
#pragma unroll
            for (int k = 0; k < 4; k++) s[t][k] = 0.f;
#pragma unroll
        for (int g = 0; g < 4; g++) {
#pragma unroll
            for (int tpl = 0; tpl < 2; tpl++) {
                const int tp = tp0 + tpl;
                const uint32_t a = sb + (tp * 16 + brow) * 144 + bkob + g * 32;
                uint32_t kh0, kh1, kh2, kh3, kl0, kl1, kl2, kl3;
                ldsm4(kh0, kh1, kh2, kh3, a);
                ldsm4(kl0, kl1, kl2, kl3, a + 9216);
                mma_bf16(s[2*tpl][0], s[2*tpl][1], s[2*tpl][2], s[2*tpl][3],
                         qa_h[g][0], qa_h[g][1], qa_h[g][2], qa_h[g][3], kh0, kh1);
                mma_bf16(s[2*tpl][0], s[2*tpl][1], s[2*tpl][2], s[2*tpl][3],
                         qa_h[g][0], qa_h[g][1], qa_h[g][2], qa_h[g][3], kl0, kl1);
                mma_bf16(s[2*tpl][0], s[2*tpl][1], s[2*tpl][2], s[2*tpl][3],
                         qa_l[g][0], qa_l[g][1], qa_l[g][2], qa_l[g][3], kh0, kh1);
                mma_bf16(s[2*tpl+1][0], s[2*tpl+1][1], s[2*tpl+1][2], s[2*tpl+1][3],
                         qa_h[g][0], qa_h[g][1], qa_h[g][2], qa_h[g][3], kh2, kh3);
                mma_bf16(s[2*tpl+1][0], s[2*tpl+1][1], s[2*tpl+1][2], s[2*tpl+1][3],
                         qa_h[g][0], qa_h[g][1], qa_h[g][2], qa_h[g][3], kl2, kl3);
                mma_bf16(s[2*tpl+1][0], s[2*tpl+1][1], s[2*tpl+1][2], s[2*tpl+1][3],
                         qa_l[g][0], qa_l[g][1], qa_l[g][2], qa_l[g][3], kh2, kh3);
            }
        }
    };

    // softmax + GEMM2 for token groups {g0, g0+1} using scores s[0..3]
    auto smax_gemm2_half = [&](float (*s)[4], int g0, uint32_t vb) {
#pragma unroll
        for (int t = 0; t < 4; t++) {
            s[t][0] = ex2f(s[t][0] - MAXC); sum0 += s[t][0];
            s[t][1] = ex2f(s[t][1] - MAXC); sum0 += s[t][1];
            s[t][2] = ex2f(s[t][2] - MAXC); sum1 += s[t][2];
            s[t][3] = ex2f(s[t][3] - MAXC); sum1 += s[t][3];
        }
#pragma unroll
        for (int gl = 0; gl < 2; gl++) {
            const int g = g0 + gl;
            uint32_t ph[4], pl[4];
#pragma unroll
            for (int hh2 = 0; hh2 < 2; hh2++) {
                const float p0 = s[2*gl + hh2][0], p1 = s[2*gl + hh2][1];
                const float p2 = s[2*gl + hh2][2], p3 = s[2*gl + hh2][3];
                const uint32_t h01 = pack_bf16x2(p0, p1);
                const uint32_t h23 = pack_bf16x2(p2, p3);
                ph[hh2 ? 2 : 0] = h01;
                ph[hh2 ? 3 : 1] = h23;
                pl[hh2 ? 2 : 0] = pack_bf16x2(
                    p0 - __uint_as_float(h01 << 16),
                    p1 - __uint_as_float(h01 & 0xffff0000u));
                pl[hh2 ? 3 : 1] = pack_bf16x2(
                    p2 - __uint_as_float(h23 << 16),
                    p3 - __uint_as_float(h23 & 0xffff0000u));
            }
#pragma unroll
            for (int dvp = 0; dvp < 4; dvp++) {
                const uint32_t a = vb + (dvp * 16 + brow) * 144 + bkob + g * 32;
                uint32_t vh0, vh1, vh2, vh3, vl0, vl1, vl2, vl3;
                ldsm4(vh0, vh1, vh2, vh3, a);
                ldsm4(vl0, vl1, vl2, vl3, a + 9216);
                mma_bf16(acc[2*dvp][0], acc[2*dvp][1], acc[2*dvp][2], acc[2*dvp][3],
                         ph[0], ph[1], ph[2], ph[3], vh0, vh1);
                mma_bf16(acc[2*dvp][0], acc[2*dvp][1], acc[2*dvp][2], acc[2*dvp][3],
                         ph[0], ph[1], ph[2], ph[3], vl0, vl1);
                mma_bf16(acc[2*dvp][0], acc[2*dvp][1], acc[2*dvp][2], acc[2*dvp][3],
                         pl[0], pl[1], pl[2], pl[3], vh0, vh1);
                mma_bf16(acc[2*dvp+1][0], acc[2*dvp+1][1], acc[2*dvp+1][2], acc[2*dvp+1][3],
                         ph[0], ph[1], ph[2], ph[3], vh2, vh3);
                mma_bf16(acc[2*dvp+1][0], acc[2*dvp+1][1], acc[2*dvp+1][2], acc[2*dvp+1][3],
                         ph[0], ph[1], ph[2], ph[3], vl2, vl3);
                mma_bf16(acc[2*dvp+1][0], acc[2*dvp+1][1], acc[2*dvp+1][2], acc[2*dvp+1][3],
                         pl[0], pl[1], pl[2], pl[3], vh2, vh3);
            }
        }
    };

    for (int kt = 0; kt < NKT; kt++) {
        // K(kt) and V(kt) fully arrived + visible to ALL threads
        cp_wait<0>();
        __syncthreads();

        if (kt + 1 < NKT) load_v(kt + 1, (kt + 1) & 1);   // full-tile overlap

        const uint32_t vb = sb + AT_VOFF + (kt & 1) * 18432;
        float s[4][4];

        // half 0: k-tokens 0..31
        gemm1_half(s, 0);
        smax_gemm2_half(s, 0, vb);

        // half 1: k-tokens 32..63 — GEMM1 is the LAST K read of this tile
        gemm1_half(s, 2);
        __syncthreads();                    // all warps done with all K reads
        if (kt + 1 < NKT) load_k(kt + 1);   // overlapped by smax+GEMM2 below
        smax_gemm2_half(s, 2, vb);
    }

    // ---- row-sum reduction across the quad
    sum0 += __shfl_xor_sync(0xffffffffu, sum0, 1);
    sum0 += __shfl_xor_sync(0xffffffffu, sum0, 2);
    sum1 += __shfl_xor_sync(0xffffffffu, sum1, 1);
    sum1 += __shfl_xor_sync(0xffffffffu, sum1, 2);
    const float inv0 = 1.f / sum0, inv1 = 1.f / sum1;

    // ---- epilogue: acc/l -> smem [64 dv][68 q] (K region, 17408 <= 18432).
    // All warps passed iter-35's mid __syncthreads after their last K read.
    float* epi = (float*)sm;
    const int qr = qw + (lid >> 2);
#pragma unroll
    for (int t = 0; t < 8; t++) {
        const int dv = t * 8 + 2 * (lid & 3);
        epi[dv * 68 + qr]           = acc[t][0] * inv0;
        epi[(dv + 1) * 68 + qr]     = acc[t][1] * inv0;
        epi[dv * 68 + qr + 8]       = acc[t][2] * inv1;
        epi[(dv + 1) * 68 + qr + 8] = acc[t][3] * inv1;
    }
    __syncthreads();

#pragma unroll
    for (int j = 0; j < 8; j++) {
        const int idx = tid + j * 128;
        const int r = idx >> 4;
        const int c4 = (idx & 15) * 4;
        const int ch = h * DQ + r;
        const float g = gamma[ch];
        float4 v = make_float4(epi[r * 68 + c4],     epi[r * 68 + c4 + 1],
                               epi[r * 68 + c4 + 2], epi[r * 68 + c4 + 3]);
        float4 scv = *(const float4*)&SC[(size_t)r * NTOK + q0 + c4];
        float4 o = make_float4(g * v.x + scv.x, g * v.y + scv.y,
                               g * v.z + scv.z, g * v.w + scv.w);
        *(float4*)&outp[((size_t)b * CH + ch) * NTOK + q0 + c4] = o;
    }
}

// ---------------------------------------------------------------------------
extern "C" void kernel_launch(void* const* d_in, const int* in_sizes, int n_in,
                              void* d_out, int out_size)
{
    const float* x     = (const float*)d_in[0];
    const float* Wq    = (const float*)d_in[1];
    const float* Wk    = (const float*)d_in[2];
    const float* Wv    = (const float*)d_in[3];
    const float* Wsc   = (const float*)d_in[4];
    const float* gamma = (const float*)d_in[5];
    float* out = (float*)d_out;

    prep_w_kernel<<<dim3(CH * CH / 256, 4), 256>>>(Wq, Wk, Wv, Wsc);
    prep_x_kernel<<<dim3(NTOK / 32, CH / 32, BATCH), dim3(32, 8)>>>(x);

    cudaFuncSetAttribute(proj_mma_kernel, cudaFuncAttributeMaxDynamicSharedMemorySize,
                         PJ_SMEM_BYTES);
    proj_mma_kernel<<<dim3(NTOK / 128, CH / 128, 16), 256, PJ_SMEM_BYTES>>>();

    cudaFuncSetAttribute(attn_mma_kernel, cudaFuncAttributeMaxDynamicSharedMemorySize,
                         AT_SMEM);
    attn_mma_kernel<<<dim3(NTOK / 64, HEADS, BATCH), 128, AT_SMEM>>>(gamma, out);
}